// round 2
// baseline (speedup 1.0000x reference)
#include <cuda_runtime.h>
#include <cuda_bf16.h>

// Problem constants
#define Bb 8
#define NSEQ 1024
#define DIM 768
#define HEADS 12
#define HD 64
#define TOPK 100
#define SCALE_F 0.125f   // 64^-0.5

#define MROWS (Bb*NSEQ)          // 8192
#define QKV_N (3*DIM)            // 2304

// Scratch (static device globals; no runtime allocation allowed)
__device__ float g_q[Bb*HEADS*NSEQ*HD];     // [B,H,N,D], pre-scaled by SCALE
__device__ float g_k[Bb*HEADS*NSEQ*HD];
__device__ float g_v[Bb*HEADS*NSEQ*HD];
__device__ float g_attn[Bb*NSEQ*DIM];       // [B,N,C] attention output

// ---------------------------------------------------------------------------
// SGEMM: C[M,N] = A[M,K] @ B[K,N]   tile 128x128x16, micro 8x8
// mode 0: scatter into g_q/g_k/g_v (QKV), q scaled
// mode 1: C = A@B + bias  (A==nullptr means A = g_attn)
// ---------------------------------------------------------------------------
#define BM 128
#define BN 128
#define BK 16

__global__ __launch_bounds__(256)
void sgemm_kernel(const float* __restrict__ A, const float* __restrict__ B,
                  float* __restrict__ C, const float* __restrict__ bias,
                  int M, int N, int K, int mode)
{
    if (A == nullptr) A = g_attn;

    __shared__ float As[BK][BM + 4];   // transposed A tile, padded
    __shared__ float Bs[BK][BN];

    const int bm = blockIdx.y * BM;
    const int bn = blockIdx.x * BN;
    const int tid = threadIdx.x;
    const int tx = tid & 15;          // 0..15 (N dir, 8 cols each)
    const int ty = tid >> 4;          // 0..15 (M dir, 8 rows each)

    float acc[8][8];
#pragma unroll
    for (int i = 0; i < 8; i++)
#pragma unroll
        for (int j = 0; j < 8; j++) acc[i][j] = 0.f;

    for (int k0 = 0; k0 < K; k0 += BK) {
        // A tile (128x16) -> transposed As[k][m]
#pragma unroll
        for (int t = 0; t < 2; t++) {
            int id  = tid + t * 256;         // 0..511
            int row = id >> 2;               // 0..127
            int c4  = id & 3;                // 0..3
            float4 a4 = *(const float4*)(A + (size_t)(bm + row) * K + k0 + c4 * 4);
            As[c4*4+0][row] = a4.x;
            As[c4*4+1][row] = a4.y;
            As[c4*4+2][row] = a4.z;
            As[c4*4+3][row] = a4.w;
        }
        // B tile (16x128)
#pragma unroll
        for (int t = 0; t < 2; t++) {
            int id  = tid + t * 256;         // 0..511
            int row = id >> 5;               // 0..15
            int c4  = id & 31;               // 0..31
            *(float4*)&Bs[row][c4 * 4] =
                *(const float4*)(B + (size_t)(k0 + row) * N + bn + c4 * 4);
        }
        __syncthreads();

#pragma unroll
        for (int kk = 0; kk < BK; kk++) {
            float a[8], b[8];
            float4 a40 = *(const float4*)&As[kk][ty * 8 + 0];
            float4 a41 = *(const float4*)&As[kk][ty * 8 + 4];
            a[0]=a40.x; a[1]=a40.y; a[2]=a40.z; a[3]=a40.w;
            a[4]=a41.x; a[5]=a41.y; a[6]=a41.z; a[7]=a41.w;
            float4 b40 = *(const float4*)&Bs[kk][tx * 8 + 0];
            float4 b41 = *(const float4*)&Bs[kk][tx * 8 + 4];
            b[0]=b40.x; b[1]=b40.y; b[2]=b40.z; b[3]=b40.w;
            b[4]=b41.x; b[5]=b41.y; b[6]=b41.z; b[7]=b41.w;
#pragma unroll
            for (int i = 0; i < 8; i++)
#pragma unroll
                for (int j = 0; j < 8; j++)
                    acc[i][j] += a[i] * b[j];
        }
        __syncthreads();
    }

    const int col0 = bn + tx * 8;
    if (mode == 0) {
        // QKV scatter. col block never straddles t (768%128==0) or head (64%8==0).
        int t = col0 / DIM;
        int r = col0 - t * DIM;
        int h = r >> 6;
        int d0 = r & 63;
        float mult = (t == 0) ? SCALE_F : 1.f;
        float* gbase = (t == 0) ? g_q : (t == 1) ? g_k : g_v;
#pragma unroll
        for (int i = 0; i < 8; i++) {
            int m  = bm + ty * 8 + i;
            int b_ = m >> 10;
            int n_ = m & 1023;
            float* dst = gbase + ((size_t)((b_ * HEADS + h) << 10) + n_) * HD + d0;
            float4 o0 = make_float4(acc[i][0]*mult, acc[i][1]*mult,
                                    acc[i][2]*mult, acc[i][3]*mult);
            float4 o1 = make_float4(acc[i][4]*mult, acc[i][5]*mult,
                                    acc[i][6]*mult, acc[i][7]*mult);
            *(float4*)(dst + 0) = o0;
            *(float4*)(dst + 4) = o1;
        }
    } else {
        float4 bi0 = *(const float4*)(bias + col0 + 0);
        float4 bi1 = *(const float4*)(bias + col0 + 4);
#pragma unroll
        for (int i = 0; i < 8; i++) {
            int m = bm + ty * 8 + i;
            float4 o0 = make_float4(acc[i][0]+bi0.x, acc[i][1]+bi0.y,
                                    acc[i][2]+bi0.z, acc[i][3]+bi0.w);
            float4 o1 = make_float4(acc[i][4]+bi1.x, acc[i][5]+bi1.y,
                                    acc[i][6]+bi1.z, acc[i][7]+bi1.w);
            *(float4*)(C + (size_t)m * N + col0 + 0) = o0;
            *(float4*)(C + (size_t)m * N + col0 + 4) = o1;
        }
    }
}

// ---------------------------------------------------------------------------
// Fused attention per (b, h, 16-row tile):
//   S: warp-per-row, 32 scores/lane in regs
//   exact top-100 threshold via binary search over monotone float order
//   masked softmax in regs -> P in smem
//   PV: 2 row-groups x 8 j-groups across 16 warps; acc[8] float4 (32 regs,
//       no spill at 128-reg cap)
// ---------------------------------------------------------------------------
#define AROWS 16
#define CHUNK 128
#define KVS 17                      // float4 stride (68 floats) -> conflict-free

// smem: q (16*64) + kv (128*68) + p (16*1024)
#define SMEM_FLOATS (AROWS*HD + CHUNK*68 + AROWS*NSEQ)
#define SMEM_BYTES  (SMEM_FLOATS * 4)

__device__ __forceinline__ float ord2f(unsigned k) {
    unsigned u = (k & 0x80000000u) ? (k & 0x7FFFFFFFu) : ~k;
    return __uint_as_float(u);
}

__global__ __launch_bounds__(512)
void attn_kernel()
{
    extern __shared__ float sm[];
    float*  sq   = sm;                       // 1024 floats
    float*  skv  = sq + AROWS * HD;          // 128*68 floats
    float*  sp   = skv + CHUNK * 68;         // 16*1024 floats
    float4* skv4 = (float4*)skv;
    float4* sp4  = (float4*)sp;

    const int tid  = threadIdx.x;
    const int lane = tid & 31;
    const int w    = tid >> 5;               // warp 0..15
    const int n0   = blockIdx.x * AROWS;
    const int h    = blockIdx.y;
    const int b    = blockIdx.z;
    const size_t base = (size_t)(b * HEADS + h) * NSEQ * HD;

    // load q tile (16 x 64)
    {
        const float4* gq4 = (const float4*)(g_q + base + (size_t)n0 * HD);
        float4* sq4 = (float4*)sq;
        for (int i = tid; i < AROWS * HD / 4; i += 512) sq4[i] = gq4[i];
    }

    // ---- S = q @ K^T : warp w owns row w, 32 scores per lane ----
    float s[32];
    const float4* gk4 = (const float4*)(g_k + base);

#pragma unroll
    for (int c = 0; c < 8; c++) {
        __syncthreads();
        for (int i = tid; i < CHUNK * 16; i += 512) {
            int row = i >> 4, d4 = i & 15;
            skv4[row * KVS + d4] = gk4[(size_t)(c * CHUNK + row) * 16 + d4];
        }
        __syncthreads();

        const float4* qrow = (const float4*)(sq + w * HD);
        float a0 = 0.f, a1 = 0.f, a2 = 0.f, a3 = 0.f;
#pragma unroll
        for (int d4 = 0; d4 < 16; d4++) {
            float4 q4 = qrow[d4];
            float4 k0v = skv4[(0 * 32 + lane) * KVS + d4];
            float4 k1v = skv4[(1 * 32 + lane) * KVS + d4];
            float4 k2v = skv4[(2 * 32 + lane) * KVS + d4];
            float4 k3v = skv4[(3 * 32 + lane) * KVS + d4];
            a0 += q4.x*k0v.x + q4.y*k0v.y + q4.z*k0v.z + q4.w*k0v.w;
            a1 += q4.x*k1v.x + q4.y*k1v.y + q4.z*k1v.z + q4.w*k1v.w;
            a2 += q4.x*k2v.x + q4.y*k2v.y + q4.z*k2v.z + q4.w*k2v.w;
            a3 += q4.x*k3v.x + q4.y*k3v.y + q4.z*k3v.z + q4.w*k3v.w;
        }
        s[c*4+0] = a0; s[c*4+1] = a1; s[c*4+2] = a2; s[c*4+3] = a3;
    }

    // ---- exact top-100 threshold: binary search in monotone key space ----
    unsigned lo = 0x007FFFFFu;     // key(-Inf)
    unsigned hi = 0xFF800000u;     // key(+Inf)
    while (lo < hi) {
        unsigned mid = lo + ((hi - lo + 1u) >> 1);
        float t = ord2f(mid);
        int cnt = 0;
#pragma unroll
        for (int i = 0; i < 32; i++) cnt += (s[i] >= t) ? 1 : 0;
#pragma unroll
        for (int o = 16; o > 0; o >>= 1)
            cnt += __shfl_xor_sync(0xffffffffu, cnt, o);
        if (cnt >= TOPK) lo = mid; else hi = mid - 1u;
    }
    const float kth = ord2f(lo);

    // ---- masked softmax ----
    float m = s[0];
#pragma unroll
    for (int i = 1; i < 32; i++) m = fmaxf(m, s[i]);
#pragma unroll
    for (int o = 16; o > 0; o >>= 1)
        m = fmaxf(m, __shfl_xor_sync(0xffffffffu, m, o));

    float sum = 0.f;
#pragma unroll
    for (int i = 0; i < 32; i++) {
        float p = (s[i] >= kth) ? __expf(s[i] - m) : 0.f;
        s[i] = p;
        sum += p;
    }
#pragma unroll
    for (int o = 16; o > 0; o >>= 1)
        sum += __shfl_xor_sync(0xffffffffu, sum, o);
    const float inv = 1.f / sum;

#pragma unroll
    for (int c = 0; c < 8; c++)
#pragma unroll
        for (int u = 0; u < 4; u++)
            sp[w * NSEQ + c * 128 + u * 32 + lane] = s[c*4+u] * inv;
    // consumed after the sync at the top of the PV loop below

    // ---- PV: warp -> (row-group rg = w&1 : 8 rows, j-group jg = w>>1 : 16 j/chunk)
    float4 acc[8];
#pragma unroll
    for (int r = 0; r < 8; r++) acc[r] = make_float4(0.f, 0.f, 0.f, 0.f);

    const int rg = w & 1;
    const int jg = w >> 1;         // 0..7
    const int d4 = lane & 15;
    const int js = lane >> 4;      // 0 or 1
    const float4* gv4 = (const float4*)(g_v + base);

#pragma unroll
    for (int c = 0; c < 8; c++) {
        __syncthreads();          // protects skv reuse AND (c==0) sp visibility
        for (int i = tid; i < CHUNK * 16; i += 512) {
            int row = i >> 4, dd = i & 15;
            skv4[row * KVS + dd] = gv4[(size_t)(c * CHUNK + row) * 16 + dd];
        }
        __syncthreads();

#pragma unroll
        for (int jj = 0; jj < 8; jj++) {
            int jl = jg * 16 + jj * 2 + js;    // local j in chunk
            int jgl = c * 128 + jl;            // global j
            float4 v4 = skv4[jl * KVS + d4];
            const float* prow = sp + (rg * 8) * NSEQ + jgl;
#pragma unroll
            for (int r = 0; r < 8; r++) {
                float p = prow[r * NSEQ];
                acc[r].x += p * v4.x;
                acc[r].y += p * v4.y;
                acc[r].z += p * v4.z;
                acc[r].w += p * v4.w;
            }
        }
    }

    // reduce js halves within warp (lane l += lane l+16)
#pragma unroll
    for (int r = 0; r < 8; r++) {
        acc[r].x += __shfl_down_sync(0xffffffffu, acc[r].x, 16);
        acc[r].y += __shfl_down_sync(0xffffffffu, acc[r].y, 16);
        acc[r].z += __shfl_down_sync(0xffffffffu, acc[r].z, 16);
        acc[r].w += __shfl_down_sync(0xffffffffu, acc[r].w, 16);
    }

    __syncthreads();              // everyone done reading sp -> reuse as buffer
    if (lane < 16) {
#pragma unroll
        for (int r = 0; r < 8; r++)
            sp4[w * 128 + r * 16 + d4] = acc[r];
    }
    __syncthreads();

    // final reduction over 8 j-groups: 256 float4 outputs
    if (tid < 256) {
        int r   = tid >> 4;        // 0..15
        int dd4 = tid & 15;
        int rgo = r >> 3;          // row group
        int rl  = r & 7;
        float4 o4 = make_float4(0.f, 0.f, 0.f, 0.f);
#pragma unroll
        for (int jgi = 0; jgi < 8; jgi++) {
            float4 t4 = sp4[(rgo + 2 * jgi) * 128 + rl * 16 + dd4];
            o4.x += t4.x; o4.y += t4.y; o4.z += t4.z; o4.w += t4.w;
        }
        float4* dst = (float4*)(g_attn + (size_t)(b * NSEQ + n0 + r) * DIM + h * HD);
        dst[dd4] = o4;
    }
}

// ---------------------------------------------------------------------------
extern "C" void kernel_launch(void* const* d_in, const int* in_sizes, int n_in,
                              void* d_out, int out_size)
{
    const float* x      = (const float*)d_in[0];
    const float* w_qkv  = (const float*)d_in[1];
    const float* w_proj = (const float*)d_in[2];
    const float* b_proj = (const float*)d_in[3];
    float* out = (float*)d_out;

    cudaFuncSetAttribute(attn_kernel,
                         cudaFuncAttributeMaxDynamicSharedMemorySize, SMEM_BYTES);

    // 1) QKV GEMM + scatter (q pre-scaled)
    sgemm_kernel<<<dim3(QKV_N / BN, MROWS / BM), 256>>>(
        x, w_qkv, nullptr, nullptr, MROWS, QKV_N, DIM, 0);

    // 2) fused attention (topk mask + softmax + PV)
    attn_kernel<<<dim3(NSEQ / AROWS, HEADS, Bb), 512, SMEM_BYTES>>>();

    // 3) output projection + bias
    sgemm_kernel<<<dim3(DIM / BN, MROWS / BM), 256>>>(
        nullptr, w_proj, out, b_proj, MROWS, DIM, DIM, 1);
}

// round 3
// speedup vs baseline: 2.4398x; 2.4398x over previous
#include <cuda_runtime.h>
#include <cuda_bf16.h>

// Problem constants
#define Bb 8
#define NSEQ 1024
#define DIM 768
#define HEADS 12
#define HD 64
#define TOPK 100
#define SCALE_F 0.125f   // 64^-0.5

#define MROWS (Bb*NSEQ)          // 8192
#define QKV_N (3*DIM)            // 2304
#define NHEAD (Bb*HEADS)         // 96
#define CAP 192                  // compact-list capacity per row

// Scratch (static device globals)
__device__ float g_q[NHEAD*NSEQ*HD];        // [B,H,N,D], pre-scaled by SCALE
__device__ float g_k[NHEAD*NSEQ*HD];
__device__ float g_v[NHEAD*NSEQ*HD];
__device__ float g_attn[Bb*NSEQ*DIM];       // [B,N,C] attention output
__device__ float g_s[(size_t)NHEAD*NSEQ*NSEQ];   // S scores (384MB)
__device__ int   g_idx[(size_t)NHEAD*NSEQ*CAP];  // compact j indices
__device__ float g_pv [(size_t)NHEAD*NSEQ*CAP];  // compact softmax probs
__device__ int   g_cnt[NHEAD*NSEQ];

// ---------------------------------------------------------------------------
// SGEMM (round-1 config): tile 128x64x16, micro 8x4, 256 threads
// mode 0: scatter into g_q/g_k/g_v (QKV), q scaled
// mode 1: C = A@B + bias  (A==nullptr means A = g_attn)
// ---------------------------------------------------------------------------
#define BM 128
#define BN 64
#define BK 16
#define TM 8
#define TN 4

__global__ __launch_bounds__(256)
void sgemm_kernel(const float* __restrict__ A, const float* __restrict__ B,
                  float* __restrict__ C, const float* __restrict__ bias,
                  int M, int N, int K, int mode)
{
    if (A == nullptr) A = g_attn;

    __shared__ float As[BK][BM + 4];
    __shared__ float Bs[BK][BN];

    const int bm = blockIdx.y * BM;
    const int bn = blockIdx.x * BN;
    const int tid = threadIdx.x;
    const int tx = tid & 15;
    const int ty = tid >> 4;

    float acc[TM][TN];
#pragma unroll
    for (int i = 0; i < TM; i++)
#pragma unroll
        for (int j = 0; j < TN; j++) acc[i][j] = 0.f;

    for (int k0 = 0; k0 < K; k0 += BK) {
#pragma unroll
        for (int t = 0; t < 2; t++) {
            int id  = tid + t * 256;
            int row = id >> 2;
            int c4  = id & 3;
            float4 a4 = *(const float4*)(A + (size_t)(bm + row) * K + k0 + c4 * 4);
            As[c4*4+0][row] = a4.x;
            As[c4*4+1][row] = a4.y;
            As[c4*4+2][row] = a4.z;
            As[c4*4+3][row] = a4.w;
        }
        {
            int row = tid >> 4;
            int c4  = tid & 15;
            *(float4*)&Bs[row][c4 * 4] =
                *(const float4*)(B + (size_t)(k0 + row) * N + bn + c4 * 4);
        }
        __syncthreads();

#pragma unroll
        for (int kk = 0; kk < BK; kk++) {
            float a[TM], b[TN];
            float4 a40 = *(const float4*)&As[kk][ty * TM + 0];
            float4 a41 = *(const float4*)&As[kk][ty * TM + 4];
            a[0]=a40.x; a[1]=a40.y; a[2]=a40.z; a[3]=a40.w;
            a[4]=a41.x; a[5]=a41.y; a[6]=a41.z; a[7]=a41.w;
            float4 b4 = *(const float4*)&Bs[kk][tx * TN];
            b[0]=b4.x; b[1]=b4.y; b[2]=b4.z; b[3]=b4.w;
#pragma unroll
            for (int i = 0; i < TM; i++)
#pragma unroll
                for (int j = 0; j < TN; j++)
                    acc[i][j] += a[i] * b[j];
        }
        __syncthreads();
    }

    if (mode == 0) {
#pragma unroll
        for (int i = 0; i < TM; i++) {
            int m  = bm + ty * TM + i;
            int b_ = m >> 10;
            int n_ = m & 1023;
#pragma unroll
            for (int j = 0; j < TN; j++) {
                int col = bn + tx * TN + j;
                int t = col / DIM;
                int r = col - t * DIM;
                int h = r >> 6;
                int d = r & 63;
                float vv = acc[i][j];
                float* dst;
                if (t == 0)      { dst = g_q; vv *= SCALE_F; }
                else if (t == 1)   dst = g_k;
                else               dst = g_v;
                dst[((size_t)((b_ * HEADS + h) << 10) + n_) * HD + d] = vv;
            }
        }
    } else {
#pragma unroll
        for (int i = 0; i < TM; i++) {
            int m = bm + ty * TM + i;
#pragma unroll
            for (int j = 0; j < TN; j++) {
                int col = bn + tx * TN + j;
                C[(size_t)m * N + col] = acc[i][j] + bias[col];
            }
        }
    }
}

// ---------------------------------------------------------------------------
// Stage A: S = q @ k^T per head. Tile 128x128, K=64 (one load phase).
// ---------------------------------------------------------------------------
#define SA_STRIDE 132
#define SA_BYTES (2 * 64 * SA_STRIDE * 4)   // 67584 B

__global__ __launch_bounds__(256)
void s_gemm_kernel()
{
    extern __shared__ float smA[];
    float (*Qs)[SA_STRIDE] = (float(*)[SA_STRIDE])smA;
    float (*Ks)[SA_STRIDE] = (float(*)[SA_STRIDE])(smA + 64 * SA_STRIDE);

    const int head = blockIdx.z;
    const float* q = g_q + (size_t)head * NSEQ * HD;
    const float* k = g_k + (size_t)head * NSEQ * HD;
    float* srow = g_s + (size_t)head * NSEQ * NSEQ;

    const int bm = blockIdx.y * 128;
    const int bn = blockIdx.x * 128;
    const int tid = threadIdx.x;
    const int tx = tid & 15;
    const int ty = tid >> 4;

    // load q/k tiles (128x64 each), store transposed [k][m]
#pragma unroll
    for (int t = 0; t < 8; t++) {
        int id  = tid + t * 256;         // 0..2047
        int row = id >> 4;               // 0..127
        int c4  = id & 15;               // 0..15
        float4 a4 = *(const float4*)(q + (size_t)(bm + row) * HD + c4 * 4);
        Qs[c4*4+0][row] = a4.x;
        Qs[c4*4+1][row] = a4.y;
        Qs[c4*4+2][row] = a4.z;
        Qs[c4*4+3][row] = a4.w;
        float4 b4 = *(const float4*)(k + (size_t)(bn + row) * HD + c4 * 4);
        Ks[c4*4+0][row] = b4.x;
        Ks[c4*4+1][row] = b4.y;
        Ks[c4*4+2][row] = b4.z;
        Ks[c4*4+3][row] = b4.w;
    }
    __syncthreads();

    float acc[8][8];
#pragma unroll
    for (int i = 0; i < 8; i++)
#pragma unroll
        for (int j = 0; j < 8; j++) acc[i][j] = 0.f;

#pragma unroll
    for (int kk = 0; kk < 64; kk++) {
        float a[8], b[8];
        float4 a40 = *(const float4*)&Qs[kk][ty * 8 + 0];
        float4 a41 = *(const float4*)&Qs[kk][ty * 8 + 4];
        a[0]=a40.x; a[1]=a40.y; a[2]=a40.z; a[3]=a40.w;
        a[4]=a41.x; a[5]=a41.y; a[6]=a41.z; a[7]=a41.w;
        float4 b40 = *(const float4*)&Ks[kk][tx * 8 + 0];
        float4 b41 = *(const float4*)&Ks[kk][tx * 8 + 4];
        b[0]=b40.x; b[1]=b40.y; b[2]=b40.z; b[3]=b40.w;
        b[4]=b41.x; b[5]=b41.y; b[6]=b41.z; b[7]=b41.w;
#pragma unroll
        for (int i = 0; i < 8; i++)
#pragma unroll
            for (int j = 0; j < 8; j++)
                acc[i][j] += a[i] * b[j];
    }

#pragma unroll
    for (int i = 0; i < 8; i++) {
        int m = bm + ty * 8 + i;
        float* dst = srow + (size_t)m * NSEQ + bn + tx * 8;
        *(float4*)(dst + 0) = make_float4(acc[i][0], acc[i][1], acc[i][2], acc[i][3]);
        *(float4*)(dst + 4) = make_float4(acc[i][4], acc[i][5], acc[i][6], acc[i][7]);
    }
}

// ---------------------------------------------------------------------------
// Stage B: per row — exact top-100 threshold (binary search in monotone key
// space), masked softmax, compact surviving (j, p) pairs.
// ---------------------------------------------------------------------------
__device__ __forceinline__ float ord2f(unsigned k) {
    unsigned u = (k & 0x80000000u) ? (k & 0x7FFFFFFFu) : ~k;
    return __uint_as_float(u);
}

__global__ __launch_bounds__(256)
void topk_kernel()
{
    const int head = blockIdx.y;
    const int warp = threadIdx.x >> 5;
    const int lane = threadIdx.x & 31;
    const int n    = blockIdx.x * 8 + warp;
    const size_t rbase = (size_t)head * NSEQ + n;
    const float* srow = g_s + rbase * NSEQ;

    float s[32];
#pragma unroll
    for (int i = 0; i < 32; i++) s[i] = srow[i * 32 + lane];

    // binary search threshold
    unsigned lo = 0x007FFFFFu;     // key(-Inf)
    unsigned hi = 0xFF800000u;     // key(+Inf)
    while (lo < hi) {
        unsigned mid = lo + ((hi - lo + 1u) >> 1);
        float t = ord2f(mid);
        int cnt = 0;
#pragma unroll
        for (int i = 0; i < 32; i++) cnt += (s[i] >= t) ? 1 : 0;
#pragma unroll
        for (int o = 16; o > 0; o >>= 1)
            cnt += __shfl_xor_sync(0xffffffffu, cnt, o);
        if (cnt >= TOPK) lo = mid; else hi = mid - 1u;
    }
    const float kth = ord2f(lo);

    // softmax over surviving entries
    float m = s[0];
#pragma unroll
    for (int i = 1; i < 32; i++) m = fmaxf(m, s[i]);
#pragma unroll
    for (int o = 16; o > 0; o >>= 1)
        m = fmaxf(m, __shfl_xor_sync(0xffffffffu, m, o));

    float sum = 0.f;
    float p[32];
#pragma unroll
    for (int i = 0; i < 32; i++) {
        bool keep = (s[i] >= kth);
        p[i] = keep ? __expf(s[i] - m) : 0.f;
        sum += p[i];
    }
#pragma unroll
    for (int o = 16; o > 0; o >>= 1)
        sum += __shfl_xor_sync(0xffffffffu, sum, o);
    const float inv = 1.f / sum;

    // compact (j, p) via ballot prefix
    int* oidx = g_idx + rbase * CAP;
    float* opv = g_pv + rbase * CAP;
    int base = 0;
#pragma unroll
    for (int i = 0; i < 32; i++) {
        bool keep = (p[i] > 0.f);
        unsigned msk = __ballot_sync(0xffffffffu, keep);
        int pos = base + __popc(msk & ((1u << lane) - 1u));
        if (keep && pos < CAP) {
            oidx[pos] = i * 32 + lane;
            opv[pos]  = p[i] * inv;
        }
        base += __popc(msk);
    }
    if (lane == 0) g_cnt[rbase] = (base < CAP) ? base : CAP;
}

// ---------------------------------------------------------------------------
// Stage C: sparse PV — warp per row, gather ~100 V rows from L2.
// ---------------------------------------------------------------------------
__global__ __launch_bounds__(256)
void pv_sparse_kernel()
{
    __shared__ int   sj[8][CAP];
    __shared__ float spv[8][CAP];

    const int head = blockIdx.y;
    const int warp = threadIdx.x >> 5;
    const int lane = threadIdx.x & 31;
    const int n    = blockIdx.x * 8 + warp;
    const size_t rbase = (size_t)head * NSEQ + n;

    const int cnt = g_cnt[rbase];
    const int* oidx = g_idx + rbase * CAP;
    const float* opv = g_pv + rbase * CAP;
    for (int i = lane; i < cnt; i += 32) {
        sj[warp][i]  = oidx[i];
        spv[warp][i] = opv[i];
    }
    __syncwarp();

    const float* V = g_v + (size_t)head * NSEQ * HD;
    float2 acc = make_float2(0.f, 0.f);
    const int d2 = lane * 2;

    int i = 0;
    for (; i + 4 <= cnt; i += 4) {
        int   j0 = sj[warp][i+0], j1 = sj[warp][i+1];
        int   j2 = sj[warp][i+2], j3 = sj[warp][i+3];
        float p0 = spv[warp][i+0], p1 = spv[warp][i+1];
        float p2 = spv[warp][i+2], p3 = spv[warp][i+3];
        float2 v0 = *(const float2*)(V + (size_t)j0 * HD + d2);
        float2 v1 = *(const float2*)(V + (size_t)j1 * HD + d2);
        float2 v2 = *(const float2*)(V + (size_t)j2 * HD + d2);
        float2 v3 = *(const float2*)(V + (size_t)j3 * HD + d2);
        acc.x += p0*v0.x + p1*v1.x + p2*v2.x + p3*v3.x;
        acc.y += p0*v0.y + p1*v1.y + p2*v2.y + p3*v3.y;
    }
    for (; i < cnt; i++) {
        int j = sj[warp][i];
        float pp = spv[warp][i];
        float2 v = *(const float2*)(V + (size_t)j * HD + d2);
        acc.x += pp * v.x;
        acc.y += pp * v.y;
    }

    const int b = head / HEADS;
    const int h = head - b * HEADS;
    float* dst = g_attn + ((size_t)(b * NSEQ + n)) * DIM + h * HD + d2;
    *(float2*)dst = acc;
}

// ---------------------------------------------------------------------------
extern "C" void kernel_launch(void* const* d_in, const int* in_sizes, int n_in,
                              void* d_out, int out_size)
{
    const float* x      = (const float*)d_in[0];
    const float* w_qkv  = (const float*)d_in[1];
    const float* w_proj = (const float*)d_in[2];
    const float* b_proj = (const float*)d_in[3];
    float* out = (float*)d_out;

    cudaFuncSetAttribute(s_gemm_kernel,
                         cudaFuncAttributeMaxDynamicSharedMemorySize, SA_BYTES);

    // 1) QKV GEMM + scatter (q pre-scaled)
    sgemm_kernel<<<dim3(QKV_N / BN, MROWS / BM), 256>>>(
        x, w_qkv, nullptr, nullptr, MROWS, QKV_N, DIM, 0);

    // 2a) S = Q @ K^T per head
    s_gemm_kernel<<<dim3(NSEQ / 128, NSEQ / 128, NHEAD), 256, SA_BYTES>>>();

    // 2b) top-k threshold + softmax + compaction
    topk_kernel<<<dim3(NSEQ / 8, NHEAD), 256>>>();

    // 2c) sparse PV gather
    pv_sparse_kernel<<<dim3(NSEQ / 8, NHEAD), 256>>>();

    // 3) output projection + bias
    sgemm_kernel<<<dim3(DIM / BN, MROWS / BM), 256>>>(
        nullptr, w_proj, out, b_proj, MROWS, DIM, DIM, 1);
}

// round 4
// speedup vs baseline: 2.4635x; 1.0097x over previous
#include <cuda_runtime.h>
#include <cuda_bf16.h>

// Problem constants
#define Bb 8
#define NSEQ 1024
#define DIM 768
#define HEADS 12
#define HD 64
#define TOPK 100
#define SCALE_F 0.125f   // 64^-0.5

#define MROWS (Bb*NSEQ)          // 8192
#define QKV_N (3*DIM)            // 2304
#define NHEAD (Bb*HEADS)         // 96
#define CAP 192                  // compact-list capacity per row

// Scratch (static device globals)
__device__ float g_q[NHEAD*NSEQ*HD];        // [B,H,N,D], pre-scaled by SCALE
__device__ float g_k[NHEAD*NSEQ*HD];
__device__ float g_v[NHEAD*NSEQ*HD];
__device__ float g_attn[Bb*NSEQ*DIM];       // [B,N,C] attention output
__device__ float g_s[(size_t)NHEAD*NSEQ*NSEQ];   // S scores (384MB)
__device__ int   g_idx[(size_t)NHEAD*NSEQ*CAP];  // compact j indices
__device__ float g_pv [(size_t)NHEAD*NSEQ*CAP];  // compact softmax probs
__device__ int   g_cnt[NHEAD*NSEQ];

// ---------------------------------------------------------------------------
// SGEMM: tile 128x64x16, micro 8x4, 256 threads, DOUBLE-BUFFERED smem with
// register prefetch (one sync per K-iteration, global latency hidden).
// mode 0: scatter into g_q/g_k/g_v (QKV), q scaled
// mode 1: C = A@B + bias  (A==nullptr means A = g_attn)
// ---------------------------------------------------------------------------
#define BM 128
#define BN 64
#define BK 16
#define TM 8
#define TN 4

__global__ __launch_bounds__(256)
void sgemm_kernel(const float* __restrict__ A, const float* __restrict__ B,
                  float* __restrict__ C, const float* __restrict__ bias,
                  int M, int N, int K, int mode)
{
    if (A == nullptr) A = g_attn;

    __shared__ float As[2][BK][BM + 4];
    __shared__ float Bs[2][BK][BN];

    const int bm = blockIdx.y * BM;
    const int bn = blockIdx.x * BN;
    const int tid = threadIdx.x;
    const int tx = tid & 15;
    const int ty = tid >> 4;

    // per-thread load coordinates
    const int ar0 = tid >> 2;            // A rows (t=0): 0..63
    const int ar1 = (tid + 256) >> 2;    // A rows (t=1): 64..127
    const int ac4 = tid & 3;             // A col group
    const int br  = tid >> 4;            // B row 0..15
    const int bc4 = tid & 15;            // B col group

    const float* Abase0 = A + (size_t)(bm + ar0) * K + ac4 * 4;
    const float* Abase1 = A + (size_t)(bm + ar1) * K + ac4 * 4;
    const float* Bbase  = B + (size_t)br * N + bn + bc4 * 4;

    float acc[TM][TN];
#pragma unroll
    for (int i = 0; i < TM; i++)
#pragma unroll
        for (int j = 0; j < TN; j++) acc[i][j] = 0.f;

    // prologue: tile 0 -> smem[0]
    {
        float4 a0 = *(const float4*)(Abase0);
        float4 a1 = *(const float4*)(Abase1);
        float4 b0 = *(const float4*)(Bbase);
        As[0][ac4*4+0][ar0] = a0.x; As[0][ac4*4+1][ar0] = a0.y;
        As[0][ac4*4+2][ar0] = a0.z; As[0][ac4*4+3][ar0] = a0.w;
        As[0][ac4*4+0][ar1] = a1.x; As[0][ac4*4+1][ar1] = a1.y;
        As[0][ac4*4+2][ar1] = a1.z; As[0][ac4*4+3][ar1] = a1.w;
        *(float4*)&Bs[0][br][bc4 * 4] = b0;
    }
    __syncthreads();

    const int nk = K / BK;
    for (int it = 0; it < nk; it++) {
        const int cur = it & 1;
        float4 pa0, pa1, pb;
        if (it + 1 < nk) {
            int k0 = (it + 1) * BK;
            pa0 = *(const float4*)(Abase0 + k0);
            pa1 = *(const float4*)(Abase1 + k0);
            pb  = *(const float4*)(Bbase + (size_t)k0 * N);
        }

#pragma unroll
        for (int kk = 0; kk < BK; kk++) {
            float a[TM], b[TN];
            float4 a40 = *(const float4*)&As[cur][kk][ty * TM + 0];
            float4 a41 = *(const float4*)&As[cur][kk][ty * TM + 4];
            a[0]=a40.x; a[1]=a40.y; a[2]=a40.z; a[3]=a40.w;
            a[4]=a41.x; a[5]=a41.y; a[6]=a41.z; a[7]=a41.w;
            float4 b4 = *(const float4*)&Bs[cur][kk][tx * TN];
            b[0]=b4.x; b[1]=b4.y; b[2]=b4.z; b[3]=b4.w;
#pragma unroll
            for (int i = 0; i < TM; i++)
#pragma unroll
                for (int j = 0; j < TN; j++)
                    acc[i][j] += a[i] * b[j];
        }

        if (it + 1 < nk) {
            const int nxt = 1 - cur;
            As[nxt][ac4*4+0][ar0] = pa0.x; As[nxt][ac4*4+1][ar0] = pa0.y;
            As[nxt][ac4*4+2][ar0] = pa0.z; As[nxt][ac4*4+3][ar0] = pa0.w;
            As[nxt][ac4*4+0][ar1] = pa1.x; As[nxt][ac4*4+1][ar1] = pa1.y;
            As[nxt][ac4*4+2][ar1] = pa1.z; As[nxt][ac4*4+3][ar1] = pa1.w;
            *(float4*)&Bs[nxt][br][bc4 * 4] = pb;
            __syncthreads();
        }
    }

    if (mode == 0) {
#pragma unroll
        for (int i = 0; i < TM; i++) {
            int m  = bm + ty * TM + i;
            int b_ = m >> 10;
            int n_ = m & 1023;
#pragma unroll
            for (int j = 0; j < TN; j++) {
                int col = bn + tx * TN + j;
                int t = col / DIM;
                int r = col - t * DIM;
                int h = r >> 6;
                int d = r & 63;
                float vv = acc[i][j];
                float* dst;
                if (t == 0)      { dst = g_q; vv *= SCALE_F; }
                else if (t == 1)   dst = g_k;
                else               dst = g_v;
                dst[((size_t)((b_ * HEADS + h) << 10) + n_) * HD + d] = vv;
            }
        }
    } else {
#pragma unroll
        for (int i = 0; i < TM; i++) {
            int m = bm + ty * TM + i;
#pragma unroll
            for (int j = 0; j < TN; j++) {
                int col = bn + tx * TN + j;
                C[(size_t)m * N + col] = acc[i][j] + bias[col];
            }
        }
    }
}

// ---------------------------------------------------------------------------
// Stage A: S = q @ k^T per head. Tile 128x128, K=64 (one load phase).
// ---------------------------------------------------------------------------
#define SA_STRIDE 132
#define SA_BYTES (2 * 64 * SA_STRIDE * 4)   // 67584 B

__global__ __launch_bounds__(256)
void s_gemm_kernel()
{
    extern __shared__ float smA[];
    float (*Qs)[SA_STRIDE] = (float(*)[SA_STRIDE])smA;
    float (*Ks)[SA_STRIDE] = (float(*)[SA_STRIDE])(smA + 64 * SA_STRIDE);

    const int head = blockIdx.z;
    const float* q = g_q + (size_t)head * NSEQ * HD;
    const float* k = g_k + (size_t)head * NSEQ * HD;
    float* srow = g_s + (size_t)head * NSEQ * NSEQ;

    const int bm = blockIdx.y * 128;
    const int bn = blockIdx.x * 128;
    const int tid = threadIdx.x;
    const int tx = tid & 15;
    const int ty = tid >> 4;

#pragma unroll
    for (int t = 0; t < 8; t++) {
        int id  = tid + t * 256;         // 0..2047
        int row = id >> 4;               // 0..127
        int c4  = id & 15;               // 0..15
        float4 a4 = *(const float4*)(q + (size_t)(bm + row) * HD + c4 * 4);
        Qs[c4*4+0][row] = a4.x;
        Qs[c4*4+1][row] = a4.y;
        Qs[c4*4+2][row] = a4.z;
        Qs[c4*4+3][row] = a4.w;
        float4 b4 = *(const float4*)(k + (size_t)(bn + row) * HD + c4 * 4);
        Ks[c4*4+0][row] = b4.x;
        Ks[c4*4+1][row] = b4.y;
        Ks[c4*4+2][row] = b4.z;
        Ks[c4*4+3][row] = b4.w;
    }
    __syncthreads();

    float acc[8][8];
#pragma unroll
    for (int i = 0; i < 8; i++)
#pragma unroll
        for (int j = 0; j < 8; j++) acc[i][j] = 0.f;

#pragma unroll
    for (int kk = 0; kk < 64; kk++) {
        float a[8], b[8];
        float4 a40 = *(const float4*)&Qs[kk][ty * 8 + 0];
        float4 a41 = *(const float4*)&Qs[kk][ty * 8 + 4];
        a[0]=a40.x; a[1]=a40.y; a[2]=a40.z; a[3]=a40.w;
        a[4]=a41.x; a[5]=a41.y; a[6]=a41.z; a[7]=a41.w;
        float4 b40 = *(const float4*)&Ks[kk][tx * 8 + 0];
        float4 b41 = *(const float4*)&Ks[kk][tx * 8 + 4];
        b[0]=b40.x; b[1]=b40.y; b[2]=b40.z; b[3]=b40.w;
        b[4]=b41.x; b[5]=b41.y; b[6]=b41.z; b[7]=b41.w;
#pragma unroll
        for (int i = 0; i < 8; i++)
#pragma unroll
            for (int j = 0; j < 8; j++)
                acc[i][j] += a[i] * b[j];
    }

#pragma unroll
    for (int i = 0; i < 8; i++) {
        int m = bm + ty * 8 + i;
        float* dst = srow + (size_t)m * NSEQ + bn + tx * 8;
        *(float4*)(dst + 0) = make_float4(acc[i][0], acc[i][1], acc[i][2], acc[i][3]);
        *(float4*)(dst + 4) = make_float4(acc[i][4], acc[i][5], acc[i][6], acc[i][7]);
    }
}

// ---------------------------------------------------------------------------
// Stage B: per row — exact top-100 threshold (binary search in monotone key
// space), masked softmax, compact surviving (j, p) pairs.
// ---------------------------------------------------------------------------
__device__ __forceinline__ float ord2f(unsigned k) {
    unsigned u = (k & 0x80000000u) ? (k & 0x7FFFFFFFu) : ~k;
    return __uint_as_float(u);
}

__global__ __launch_bounds__(256)
void topk_kernel()
{
    const int head = blockIdx.y;
    const int warp = threadIdx.x >> 5;
    const int lane = threadIdx.x & 31;
    const int n    = blockIdx.x * 8 + warp;
    const size_t rbase = (size_t)head * NSEQ + n;
    const float* srow = g_s + rbase * NSEQ;

    float s[32];
#pragma unroll
    for (int i = 0; i < 32; i++) s[i] = srow[i * 32 + lane];

    unsigned lo = 0x007FFFFFu;     // key(-Inf)
    unsigned hi = 0xFF800000u;     // key(+Inf)
    while (lo < hi) {
        unsigned mid = lo + ((hi - lo + 1u) >> 1);
        float t = ord2f(mid);
        int cnt = 0;
#pragma unroll
        for (int i = 0; i < 32; i++) cnt += (s[i] >= t) ? 1 : 0;
#pragma unroll
        for (int o = 16; o > 0; o >>= 1)
            cnt += __shfl_xor_sync(0xffffffffu, cnt, o);
        if (cnt >= TOPK) lo = mid; else hi = mid - 1u;
    }
    const float kth = ord2f(lo);

    float m = s[0];
#pragma unroll
    for (int i = 1; i < 32; i++) m = fmaxf(m, s[i]);
#pragma unroll
    for (int o = 16; o > 0; o >>= 1)
        m = fmaxf(m, __shfl_xor_sync(0xffffffffu, m, o));

    float sum = 0.f;
    float p[32];
#pragma unroll
    for (int i = 0; i < 32; i++) {
        bool keep = (s[i] >= kth);
        p[i] = keep ? __expf(s[i] - m) : 0.f;
        sum += p[i];
    }
#pragma unroll
    for (int o = 16; o > 0; o >>= 1)
        sum += __shfl_xor_sync(0xffffffffu, sum, o);
    const float inv = 1.f / sum;

    int* oidx = g_idx + rbase * CAP;
    float* opv = g_pv + rbase * CAP;
    int base = 0;
#pragma unroll
    for (int i = 0; i < 32; i++) {
        bool keep = (p[i] > 0.f);
        unsigned msk = __ballot_sync(0xffffffffu, keep);
        int pos = base + __popc(msk & ((1u << lane) - 1u));
        if (keep && pos < CAP) {
            oidx[pos] = i * 32 + lane;
            opv[pos]  = p[i] * inv;
        }
        base += __popc(msk);
    }
    if (lane == 0) g_cnt[rbase] = (base < CAP) ? base : CAP;
}

// ---------------------------------------------------------------------------
// Stage C: sparse PV — 2 rows per warp (float4 per lane-half), gather from L2.
// ---------------------------------------------------------------------------
__global__ __launch_bounds__(256)
void pv_sparse_kernel()
{
    __shared__ int   sj[16][CAP];
    __shared__ float spv[16][CAP];

    const int head = blockIdx.y;
    const int warp = threadIdx.x >> 5;
    const int lane = threadIdx.x & 31;
    const int half = lane >> 4;            // 0: row r0, 1: row r1
    const int d4   = lane & 15;            // float4 index within row (d = d4*4)
    const int r0   = blockIdx.x * 16 + warp * 2;
    const int myrow = warp * 2 + half;
    const size_t rb0 = (size_t)head * NSEQ + r0;

    // stage compact lists for both rows
    const int cnt0 = g_cnt[rb0];
    const int cnt1 = g_cnt[rb0 + 1];
    {
        const int* i0 = g_idx + rb0 * CAP;
        const float* p0 = g_pv + rb0 * CAP;
        const int* i1 = g_idx + (rb0 + 1) * CAP;
        const float* p1 = g_pv + (rb0 + 1) * CAP;
        for (int i = lane; i < cnt0; i += 32) {
            sj[warp*2+0][i]  = i0[i];
            spv[warp*2+0][i] = p0[i];
        }
        for (int i = lane; i < cnt1; i += 32) {
            sj[warp*2+1][i]  = i1[i];
            spv[warp*2+1][i] = p1[i];
        }
    }
    __syncwarp();

    const int mycnt = half ? cnt1 : cnt0;
    const int maxcnt = (cnt0 > cnt1) ? cnt0 : cnt1;

    const float* V = g_v + (size_t)head * NSEQ * HD;
    float4 acc = make_float4(0.f, 0.f, 0.f, 0.f);

    for (int i = 0; i < maxcnt; i++) {
        bool act = (i < mycnt);
        int j    = act ? sj[myrow][i] : 0;
        float pp = act ? spv[myrow][i] : 0.f;
        float4 v = *(const float4*)(V + (size_t)j * HD + d4 * 4);
        acc.x += pp * v.x;
        acc.y += pp * v.y;
        acc.z += pp * v.z;
        acc.w += pp * v.w;
    }

    const int b = head / HEADS;
    const int h = head - b * HEADS;
    float* dst = g_attn + ((size_t)(b * NSEQ + r0 + half)) * DIM + h * HD + d4 * 4;
    *(float4*)dst = acc;
}

// ---------------------------------------------------------------------------
extern "C" void kernel_launch(void* const* d_in, const int* in_sizes, int n_in,
                              void* d_out, int out_size)
{
    const float* x      = (const float*)d_in[0];
    const float* w_qkv  = (const float*)d_in[1];
    const float* w_proj = (const float*)d_in[2];
    const float* b_proj = (const float*)d_in[3];
    float* out = (float*)d_out;

    cudaFuncSetAttribute(s_gemm_kernel,
                         cudaFuncAttributeMaxDynamicSharedMemorySize, SA_BYTES);

    // 1) QKV GEMM + scatter (q pre-scaled)
    sgemm_kernel<<<dim3(QKV_N / BN, MROWS / BM), 256>>>(
        x, w_qkv, nullptr, nullptr, MROWS, QKV_N, DIM, 0);

    // 2a) S = Q @ K^T per head
    s_gemm_kernel<<<dim3(NSEQ / 128, NSEQ / 128, NHEAD), 256, SA_BYTES>>>();

    // 2b) top-k threshold + softmax + compaction
    topk_kernel<<<dim3(NSEQ / 8, NHEAD), 256>>>();

    // 2c) sparse PV gather (2 rows per warp)
    pv_sparse_kernel<<<dim3(NSEQ / 16, NHEAD), 256>>>();

    // 3) output projection + bias
    sgemm_kernel<<<dim3(DIM / BN, MROWS / BM), 256>>>(
        nullptr, w_proj, out, b_proj, MROWS, DIM, DIM, 1);
}

// round 8
// speedup vs baseline: 2.5947x; 1.0532x over previous
#include <cuda_runtime.h>
#include <cuda_bf16.h>
#include <cstdint>

// Problem constants
#define Bb 8
#define NSEQ 1024
#define DIM 768
#define HEADS 12
#define HD 64
#define TOPK 100
#define SCALE_F 0.125f

#define MROWS (Bb*NSEQ)          // 8192
#define QKV_N (3*DIM)            // 2304
#define NHEAD (Bb*HEADS)         // 96
#define CAP 192

// ---------------- scratch ----------------
__device__ __align__(16) float g_q[NHEAD*NSEQ*HD];     // pre-scaled by SCALE
__device__ __align__(16) float g_k[NHEAD*NSEQ*HD];
__device__ __align__(16) float g_v[NHEAD*NSEQ*HD];
__device__ __align__(16) float g_attn[MROWS*DIM];
__device__ __align__(16) float g_s[(size_t)NHEAD*NSEQ*NSEQ];
__device__ int   g_idx[(size_t)NHEAD*NSEQ*CAP];
__device__ float g_pv [(size_t)NHEAD*NSEQ*CAP];
__device__ int   g_cnt[NHEAD*NSEQ];

// ---------------------------------------------------------------------------
// fp32 SGEMM (round-4, PROVEN): tile 128x64x16, micro 8x4, double-buffered.
// mode 0: QKV scatter (q scaled); mode 1: C = A@B + bias (A=nullptr -> g_attn)
// ---------------------------------------------------------------------------
#define BM 128
#define BN 64
#define BK 16
#define TM 8
#define TN 4

__global__ __launch_bounds__(256)
void sgemm_kernel(const float* __restrict__ A, const float* __restrict__ B,
                  float* __restrict__ C, const float* __restrict__ bias,
                  int M, int N, int K, int mode)
{
    if (A == nullptr) A = g_attn;

    __shared__ float As[2][BK][BM + 4];
    __shared__ float Bs[2][BK][BN];

    const int bm = blockIdx.y * BM;
    const int bn = blockIdx.x * BN;
    const int tid = threadIdx.x;
    const int tx = tid & 15;
    const int ty = tid >> 4;

    const int ar0 = tid >> 2;
    const int ar1 = (tid + 256) >> 2;
    const int ac4 = tid & 3;
    const int br  = tid >> 4;
    const int bc4 = tid & 15;

    const float* Abase0 = A + (size_t)(bm + ar0) * K + ac4 * 4;
    const float* Abase1 = A + (size_t)(bm + ar1) * K + ac4 * 4;
    const float* Bbase  = B + (size_t)br * N + bn + bc4 * 4;

    float acc[TM][TN];
#pragma unroll
    for (int i = 0; i < TM; i++)
#pragma unroll
        for (int j = 0; j < TN; j++) acc[i][j] = 0.f;

    {
        float4 a0 = *(const float4*)(Abase0);
        float4 a1 = *(const float4*)(Abase1);
        float4 b0 = *(const float4*)(Bbase);
        As[0][ac4*4+0][ar0] = a0.x; As[0][ac4*4+1][ar0] = a0.y;
        As[0][ac4*4+2][ar0] = a0.z; As[0][ac4*4+3][ar0] = a0.w;
        As[0][ac4*4+0][ar1] = a1.x; As[0][ac4*4+1][ar1] = a1.y;
        As[0][ac4*4+2][ar1] = a1.z; As[0][ac4*4+3][ar1] = a1.w;
        *(float4*)&Bs[0][br][bc4 * 4] = b0;
    }
    __syncthreads();

    const int nk = K / BK;
    for (int it = 0; it < nk; it++) {
        const int cur = it & 1;
        float4 pa0, pa1, pb;
        if (it + 1 < nk) {
            int k0 = (it + 1) * BK;
            pa0 = *(const float4*)(Abase0 + k0);
            pa1 = *(const float4*)(Abase1 + k0);
            pb  = *(const float4*)(Bbase + (size_t)k0 * N);
        }

#pragma unroll
        for (int kk = 0; kk < BK; kk++) {
            float a[TM], b[TN];
            float4 a40 = *(const float4*)&As[cur][kk][ty * TM + 0];
            float4 a41 = *(const float4*)&As[cur][kk][ty * TM + 4];
            a[0]=a40.x; a[1]=a40.y; a[2]=a40.z; a[3]=a40.w;
            a[4]=a41.x; a[5]=a41.y; a[6]=a41.z; a[7]=a41.w;
            float4 b4 = *(const float4*)&Bs[cur][kk][tx * TN];
            b[0]=b4.x; b[1]=b4.y; b[2]=b4.z; b[3]=b4.w;
#pragma unroll
            for (int i = 0; i < TM; i++)
#pragma unroll
                for (int j = 0; j < TN; j++)
                    acc[i][j] += a[i] * b[j];
        }

        if (it + 1 < nk) {
            const int nxt = 1 - cur;
            As[nxt][ac4*4+0][ar0] = pa0.x; As[nxt][ac4*4+1][ar0] = pa0.y;
            As[nxt][ac4*4+2][ar0] = pa0.z; As[nxt][ac4*4+3][ar0] = pa0.w;
            As[nxt][ac4*4+0][ar1] = pa1.x; As[nxt][ac4*4+1][ar1] = pa1.y;
            As[nxt][ac4*4+2][ar1] = pa1.z; As[nxt][ac4*4+3][ar1] = pa1.w;
            *(float4*)&Bs[nxt][br][bc4 * 4] = pb;
            __syncthreads();
        }
    }

    if (mode == 0) {
#pragma unroll
        for (int i = 0; i < TM; i++) {
            int m  = bm + ty * TM + i;
            int b_ = m >> 10;
            int n_ = m & 1023;
#pragma unroll
            for (int j = 0; j < TN; j++) {
                int col = bn + tx * TN + j;
                int t = col / DIM;
                int r = col - t * DIM;
                int h = r >> 6;
                int d = r & 63;
                float vv = acc[i][j];
                float* dst;
                if (t == 0)      { dst = g_q; vv *= SCALE_F; }
                else if (t == 1)   dst = g_k;
                else               dst = g_v;
                dst[((size_t)((b_ * HEADS + h) << 10) + n_) * HD + d] = vv;
            }
        }
    } else {
#pragma unroll
        for (int i = 0; i < TM; i++) {
            int m = bm + ty * TM + i;
#pragma unroll
            for (int j = 0; j < TN; j++) {
                int col = bn + tx * TN + j;
                C[(size_t)m * N + col] = acc[i][j] + bias[col];
            }
        }
    }
}

// ---------------------------------------------------------------------------
// 3xTF32 S-GEMM: S[head](128x128) = Q(128x64) @ K(128x64)^T
// mma.sync.m16n8k8.tf32, hi/lo split in registers, fp32 smem (no packing).
// 512 threads = 4x4 warps, warp tile 32x32.
// ---------------------------------------------------------------------------
#define SSTR 68
#define S_SMEM (2*128*SSTR*4)     // 69632 B

#define MMA_TF32(d, a, b)                                                   \
    asm volatile("mma.sync.aligned.m16n8k8.row.col.f32.tf32.tf32.f32 "      \
        "{%0,%1,%2,%3}, {%4,%5,%6,%7}, {%8,%9}, {%0,%1,%2,%3};"             \
        : "+f"((d)[0]), "+f"((d)[1]), "+f"((d)[2]), "+f"((d)[3])            \
        : "r"((a)[0]), "r"((a)[1]), "r"((a)[2]), "r"((a)[3]),               \
          "r"((b)[0]), "r"((b)[1]))

__device__ __forceinline__ void tf32_split(float f, uint32_t& hi, uint32_t& lo) {
    uint32_t h;
    asm("cvt.rna.tf32.f32 %0, %1;" : "=r"(h) : "f"(f));
    float hf = __uint_as_float(h);
    asm("cvt.rna.tf32.f32 %0, %1;" : "=r"(lo) : "f"(f - hf));
    hi = h;
}

__global__ __launch_bounds__(512)
void mma_s_tf32()
{
    extern __shared__ float sm[];
    float* Qs = sm;                 // [128][SSTR]
    float* Ks = sm + 128 * SSTR;

    const int tid  = threadIdx.x;
    const int wid  = tid >> 5;
    const int lane = tid & 31;
    const int gid  = lane >> 2;     // 0..7
    const int tig  = lane & 3;      // 0..3
    const int wm   = wid & 3;       // warp M 0..3 (32 rows)
    const int wn   = wid >> 2;      // warp N 0..3 (32 cols)
    const int bm   = blockIdx.y * 128;
    const int bn   = blockIdx.x * 128;
    const int head = blockIdx.z;

    const float* q = g_q + (size_t)head * NSEQ * HD;
    const float* k = g_k + (size_t)head * NSEQ * HD;

    // load Q/K tiles (128x64 fp32 each), row-major, stride SSTR
#pragma unroll
    for (int t = 0; t < 4; t++) {
        int id  = tid + t * 512;     // 0..2047
        int row = id >> 4;           // 0..127
        int c4  = (id & 15) * 4;     // 0..60
        *(float4*)&Qs[row * SSTR + c4] = *(const float4*)(q + (size_t)(bm + row) * HD + c4);
        *(float4*)&Ks[row * SSTR + c4] = *(const float4*)(k + (size_t)(bn + row) * HD + c4);
    }
    __syncthreads();

    float d[2][4][4];
#pragma unroll
    for (int mi = 0; mi < 2; mi++)
#pragma unroll
        for (int nj = 0; nj < 4; nj++)
#pragma unroll
            for (int e = 0; e < 4; e++) d[mi][nj][e] = 0.f;

#pragma unroll
    for (int ks = 0; ks < 8; ks++) {
        const int k0 = ks * 8;

        // A fragments (m16n8k8 tf32): a0=(gid,tig) a1=(gid+8,tig)
        //                             a2=(gid,tig+4) a3=(gid+8,tig+4)
        uint32_t ah[2][4], al[2][4];
#pragma unroll
        for (int mi = 0; mi < 2; mi++) {
            int r0 = wm * 32 + mi * 16 + gid;
            tf32_split(Qs[r0 * SSTR + k0 + tig],           ah[mi][0], al[mi][0]);
            tf32_split(Qs[(r0 + 8) * SSTR + k0 + tig],     ah[mi][1], al[mi][1]);
            tf32_split(Qs[r0 * SSTR + k0 + tig + 4],       ah[mi][2], al[mi][2]);
            tf32_split(Qs[(r0 + 8) * SSTR + k0 + tig + 4], ah[mi][3], al[mi][3]);
        }
        // B fragments: b0=(k=tig, n=gid), b1=(k=tig+4, n=gid); B stored [N][K]
        uint32_t bh[4][2], bl[4][2];
#pragma unroll
        for (int nj = 0; nj < 4; nj++) {
            int n = wn * 32 + nj * 8 + gid;
            tf32_split(Ks[n * SSTR + k0 + tig],     bh[nj][0], bl[nj][0]);
            tf32_split(Ks[n * SSTR + k0 + tig + 4], bh[nj][1], bl[nj][1]);
        }

#pragma unroll
        for (int mi = 0; mi < 2; mi++)
#pragma unroll
            for (int nj = 0; nj < 4; nj++) {
                MMA_TF32(d[mi][nj], ah[mi], bh[nj]);
                MMA_TF32(d[mi][nj], ah[mi], bl[nj]);
                MMA_TF32(d[mi][nj], al[mi], bh[nj]);
            }
    }

    // epilogue: c0,c1=(row gid, col tig*2,+1); c2,c3=(row gid+8, ...)
    float* sdst = g_s + (size_t)head * NSEQ * NSEQ;
#pragma unroll
    for (int mi = 0; mi < 2; mi++)
#pragma unroll
        for (int nj = 0; nj < 4; nj++)
#pragma unroll
            for (int hf = 0; hf < 2; hf++) {
                const int m   = bm + wm * 32 + mi * 16 + gid + hf * 8;
                const int col = bn + wn * 32 + nj * 8 + tig * 2;
                *(float2*)(sdst + (size_t)m * NSEQ + col) =
                    make_float2(d[mi][nj][hf * 2 + 0], d[mi][nj][hf * 2 + 1]);
            }
}

// ---------------------------------------------------------------------------
// top-k threshold + masked softmax + compaction (PROVEN)
// ---------------------------------------------------------------------------
__device__ __forceinline__ float ord2f(unsigned k) {
    unsigned u = (k & 0x80000000u) ? (k & 0x7FFFFFFFu) : ~k;
    return __uint_as_float(u);
}

__global__ __launch_bounds__(256)
void topk_kernel()
{
    const int head = blockIdx.y;
    const int warp = threadIdx.x >> 5;
    const int lane = threadIdx.x & 31;
    const int n    = blockIdx.x * 8 + warp;
    const size_t rbase = (size_t)head * NSEQ + n;
    const float* srow = g_s + rbase * NSEQ;

    float s[32];
#pragma unroll
    for (int i = 0; i < 32; i++) s[i] = srow[i * 32 + lane];

    unsigned lo = 0x007FFFFFu;
    unsigned hi = 0xFF800000u;
    while (lo < hi) {
        unsigned mid = lo + ((hi - lo + 1u) >> 1);
        float t = ord2f(mid);
        int cnt = 0;
#pragma unroll
        for (int i = 0; i < 32; i++) cnt += (s[i] >= t) ? 1 : 0;
#pragma unroll
        for (int o = 16; o > 0; o >>= 1)
            cnt += __shfl_xor_sync(0xffffffffu, cnt, o);
        if (cnt >= TOPK) lo = mid; else hi = mid - 1u;
    }
    const float kth = ord2f(lo);

    float m = s[0];
#pragma unroll
    for (int i = 1; i < 32; i++) m = fmaxf(m, s[i]);
#pragma unroll
    for (int o = 16; o > 0; o >>= 1)
        m = fmaxf(m, __shfl_xor_sync(0xffffffffu, m, o));

    float sum = 0.f;
    float p[32];
#pragma unroll
    for (int i = 0; i < 32; i++) {
        bool keep = (s[i] >= kth);
        p[i] = keep ? __expf(s[i] - m) : 0.f;
        sum += p[i];
    }
#pragma unroll
    for (int o = 16; o > 0; o >>= 1)
        sum += __shfl_xor_sync(0xffffffffu, sum, o);
    const float inv = 1.f / sum;

    int* oidx = g_idx + rbase * CAP;
    float* opv = g_pv + rbase * CAP;
    int base = 0;
#pragma unroll
    for (int i = 0; i < 32; i++) {
        bool keep = (p[i] > 0.f);
        unsigned msk = __ballot_sync(0xffffffffu, keep);
        int pos = base + __popc(msk & ((1u << lane) - 1u));
        if (keep && pos < CAP) {
            oidx[pos] = i * 32 + lane;
            opv[pos]  = p[i] * inv;
        }
        base += __popc(msk);
    }
    if (lane == 0) g_cnt[rbase] = (base < CAP) ? base : CAP;
}

// ---------------------------------------------------------------------------
// sparse PV (round-3 PROVEN, 1 row/warp)
// ---------------------------------------------------------------------------
__global__ __launch_bounds__(256)
void pv_sparse_kernel()
{
    __shared__ int   sj[8][CAP];
    __shared__ float spv[8][CAP];

    const int head = blockIdx.y;
    const int warp = threadIdx.x >> 5;
    const int lane = threadIdx.x & 31;
    const int n    = blockIdx.x * 8 + warp;
    const size_t rbase = (size_t)head * NSEQ + n;

    const int cnt = g_cnt[rbase];
    const int* oidx = g_idx + rbase * CAP;
    const float* opv = g_pv + rbase * CAP;
    for (int i = lane; i < cnt; i += 32) {
        sj[warp][i]  = oidx[i];
        spv[warp][i] = opv[i];
    }
    __syncwarp();

    const float* V = g_v + (size_t)head * NSEQ * HD;
    float2 acc = make_float2(0.f, 0.f);
    const int d2 = lane * 2;

    int i = 0;
    for (; i + 4 <= cnt; i += 4) {
        int   j0 = sj[warp][i+0], j1 = sj[warp][i+1];
        int   j2 = sj[warp][i+2], j3 = sj[warp][i+3];
        float p0 = spv[warp][i+0], p1 = spv[warp][i+1];
        float p2 = spv[warp][i+2], p3 = spv[warp][i+3];
        float2 v0 = *(const float2*)(V + (size_t)j0 * HD + d2);
        float2 v1 = *(const float2*)(V + (size_t)j1 * HD + d2);
        float2 v2 = *(const float2*)(V + (size_t)j2 * HD + d2);
        float2 v3 = *(const float2*)(V + (size_t)j3 * HD + d2);
        acc.x += p0*v0.x + p1*v1.x + p2*v2.x + p3*v3.x;
        acc.y += p0*v0.y + p1*v1.y + p2*v2.y + p3*v3.y;
    }
    for (; i < cnt; i++) {
        int j = sj[warp][i];
        float pp = spv[warp][i];
        float2 v = *(const float2*)(V + (size_t)j * HD + d2);
        acc.x += pp * v.x;
        acc.y += pp * v.y;
    }

    const int b = head / HEADS;
    const int h = head - b * HEADS;
    float* dst = g_attn + ((size_t)(b * NSEQ + n)) * DIM + h * HD + d2;
    *(float2*)dst = acc;
}

// ---------------------------------------------------------------------------
extern "C" void kernel_launch(void* const* d_in, const int* in_sizes, int n_in,
                              void* d_out, int out_size)
{
    const float* x      = (const float*)d_in[0];
    const float* w_qkv  = (const float*)d_in[1];
    const float* w_proj = (const float*)d_in[2];
    const float* b_proj = (const float*)d_in[3];
    float* out = (float*)d_out;

    cudaFuncSetAttribute(mma_s_tf32,
                         cudaFuncAttributeMaxDynamicSharedMemorySize, S_SMEM);

    // 1) QKV GEMM (fp32, proven) + scatter
    sgemm_kernel<<<dim3(QKV_N / BN, MROWS / BM), 256>>>(
        x, w_qkv, nullptr, nullptr, MROWS, QKV_N, DIM, 0);

    // 2a) S = Q @ K^T per head (3xTF32 mma.sync — the piece under test)
    mma_s_tf32<<<dim3(NSEQ / 128, NSEQ / 128, NHEAD), 512, S_SMEM>>>();

    // 2b) top-k + softmax + compaction
    topk_kernel<<<dim3(NSEQ / 8, NHEAD), 256>>>();

    // 2c) sparse PV gather
    pv_sparse_kernel<<<dim3(NSEQ / 8, NHEAD), 256>>>();

    // 3) output projection + bias (fp32, proven)
    sgemm_kernel<<<dim3(DIM / BN, MROWS / BM), 256>>>(
        nullptr, w_proj, out, b_proj, MROWS, DIM, DIM, 1);
}